// round 2
// baseline (speedup 1.0000x reference)
#include <cuda_runtime.h>
#include <cstdint>

#define BB 64
#define TT 1024
#define KK 256
#define HALF 128
#define SROWS 224          // transT rows cached in backtrace SMEM (224 KB)

// ---------------- scratch ---------------------------------------------------
__device__ float g_state[TT * BB * KK];    // all forward states, 64 MB
__device__ float g_transT[KK * KK];        // transposed transitions

// ---------------- helpers ---------------------------------------------------
__device__ __forceinline__ uint32_t smem_u32(const void* p) {
    return (uint32_t)__cvta_generic_to_shared(p);
}

// monotone float->u32 map: preserves ordering exactly (finite values)
__device__ __forceinline__ unsigned fmono(float f) {
    int b = __float_as_int(f);
    return (unsigned)(b ^ ((b >> 31) | 0x80000000));
}

__device__ __forceinline__ void cluster_sync_all() {
    asm volatile("barrier.cluster.arrive.aligned;" ::: "memory");
    asm volatile("barrier.cluster.wait.aligned;" ::: "memory");
}

__device__ __forceinline__ uint32_t mapa_peer(uint32_t laddr, unsigned peer) {
    uint32_t raddr;
    asm volatile("mapa.shared::cluster.u32 %0, %1, %2;"
                 : "=r"(raddr) : "r"(laddr), "r"(peer));
    return raddr;
}

__device__ __forceinline__ void mbar_init(uint32_t addr, unsigned count) {
    asm volatile("mbarrier.init.shared.b64 [%0], %1;" :: "r"(addr), "r"(count) : "memory");
}
__device__ __forceinline__ void mbar_arrive_local(uint32_t addr) {
    asm volatile("mbarrier.arrive.shared.b64 _, [%0];" :: "r"(addr) : "memory");
}
__device__ __forceinline__ void mbar_arrive_remote(uint32_t raddr) {
    asm volatile("mbarrier.arrive.release.cluster.shared::cluster.b64 _, [%0];"
                 :: "r"(raddr) : "memory");
}
__device__ __forceinline__ void mbar_wait_cluster(uint32_t addr, unsigned parity) {
    asm volatile(
        "{\n\t"
        ".reg .pred P1;\n\t"
        "WAIT_%=:\n\t"
        "mbarrier.try_wait.parity.acquire.cluster.shared::cta.b64 P1, [%0], %1, 0x989680;\n\t"
        "@P1 bra.uni DONE_%=;\n\t"
        "bra.uni WAIT_%=;\n\t"
        "DONE_%=:\n\t"
        "}"
        :: "r"(addr), "r"(parity) : "memory");
}
__device__ __forceinline__ void st_cluster_f32(uint32_t raddr, float v) {
    asm volatile("st.shared::cluster.f32 [%0], %1;" :: "r"(raddr), "f"(v) : "memory");
}

// ---------------- transpose kernel ------------------------------------------
__global__ void transpose_kernel(const float* __restrict__ trans)
{
    __shared__ float tile[32][33];
    int bx = blockIdx.x, by = blockIdx.y;
    int x = bx * 32 + threadIdx.x;
    #pragma unroll
    for (int r = 0; r < 4; ++r) {
        int y = by * 32 + threadIdx.y + r * 8;
        tile[threadIdx.y + r * 8][threadIdx.x] = trans[y * KK + x];
    }
    __syncthreads();
    int x2 = by * 32 + threadIdx.x;
    #pragma unroll
    for (int r = 0; r < 4; ++r) {
        int y2 = bx * 32 + threadIdx.y + r * 8;
        g_transT[y2 * KK + x2] = tile[threadIdx.x][threadIdx.y + r * 8];
    }
}

// ---------------- forward kernel (values only) ------------------------------
// 2-CTA cluster per batch. CTA rank owns trans columns [rank*128, rank*128+128),
// held entirely in registers. Thread layout within warp w: lane = g*4 + q,
// g = i-subgroup (0..7, i = k*8+g), q = j-quad (0..3, j_local = w*16+q*4..+3).
__global__ void __cluster_dims__(2, 1, 1) __launch_bounds__(256, 1)
fwd_kernel(const float* __restrict__ em, const float* __restrict__ trans)
{
    __shared__ float st[2][KK];
    __shared__ __align__(8) unsigned long long mbar;

    const int bid  = blockIdx.x;
    const int b    = bid >> 1;
    const unsigned rank = bid & 1;
    const unsigned peer = rank ^ 1u;
    const int tid  = threadIdx.x;
    const int w    = tid >> 5;
    const int lane = tid & 31;
    const int q    = lane & 3;
    const int g    = lane >> 2;
    const int jbase = w * 16 + q * 4;         // local j quad base (0..124)
    const int jcol  = rank * HALF + jbase;    // global j column base

    const uint32_t mbar_l = smem_u32(&mbar);

    if (tid == 0) mbar_init(mbar_l, 16);      // 8 own warps + 8 peer warps per phase

    // trans quad into registers: tr[k] = trans[k*8+g][jcol..jcol+3]
    float4 tr[32];
    #pragma unroll
    for (int k = 0; k < 32; ++k)
        tr[k] = *(const float4*)&trans[(k * 8 + g) * KK + jcol];

    // initial state = emissions[b,0,:]
    {
        float v = em[(b * TT) * KK + tid];
        st[0][tid] = v;
        if (rank == 0) g_state[b * KK + tid] = v;   // row t=0
    }
    __syncthreads();
    cluster_sync_all();     // peer mbar init + both st[0] ready

    const uint32_t mbar_r = mapa_peer(mbar_l, peer);
    unsigned par = 0;

    for (int t = 1; t < TT; ++t) {
        const float* cur = st[(t + 1) & 1];
        float*       nxt = st[t & 1];

        // prefetch emission quad (writer lanes only)
        float4 em4 = make_float4(0.f, 0.f, 0.f, 0.f);
        if (lane < 4)
            em4 = __ldg((const float4*)&em[((b * TT + t) * KK) + rank * HALF + w * 16 + lane * 4]);

        // value-only max over this thread's 32 i's (i = k*8+g)
        float a0, a1, a2, a3;
        {
            float sv = cur[g];
            a0 = sv + tr[0].x; a1 = sv + tr[0].y; a2 = sv + tr[0].z; a3 = sv + tr[0].w;
        }
        #pragma unroll
        for (int k = 1; k < 32; ++k) {
            float sv = cur[k * 8 + g];
            a0 = fmaxf(a0, sv + tr[k].x);
            a1 = fmaxf(a1, sv + tr[k].y);
            a2 = fmaxf(a2, sv + tr[k].z);
            a3 = fmaxf(a3, sv + tr[k].w);
        }

        // butterfly max over the 8 i-subgroups (lanes with same q)
        #pragma unroll
        for (int off = 4; off <= 16; off <<= 1) {
            a0 = fmaxf(a0, __shfl_xor_sync(0xffffffffu, a0, off));
            a1 = fmaxf(a1, __shfl_xor_sync(0xffffffffu, a1, off));
            a2 = fmaxf(a2, __shfl_xor_sync(0xffffffffu, a2, off));
            a3 = fmaxf(a3, __shfl_xor_sync(0xffffffffu, a3, off));
        }

        if (lane < 4) {
            float4 ns = make_float4(a0 + em4.x, a1 + em4.y, a2 + em4.z, a3 + em4.w);
            const int jf = rank * HALF + w * 16 + lane * 4;
            *(float4*)&nxt[jf] = ns;                              // local half
            uint32_t r = mapa_peer(smem_u32(&nxt[jf]), peer);     // peer's copy
            st_cluster_f32(r,      ns.x);
            st_cluster_f32(r + 4,  ns.y);
            st_cluster_f32(r + 8,  ns.z);
            st_cluster_f32(r + 12, ns.w);
            *(float4*)&g_state[(t * BB + b) * KK + jf] = ns;      // for backtrace
        }
        __syncwarp();
        if (lane == 0) {
            mbar_arrive_local(mbar_l);
            mbar_arrive_remote(mbar_r);
        }
        mbar_wait_cluster(mbar_l, par);
        par ^= 1u;
    }
}

// ---------------- backtrace: serial argmax recompute along decoded path -----
// One CTA per batch. transT rows [0,SROWS) cached in SMEM; rest from L2.
// Warp 0 runs the 1023-step chain with depth-4 register prefetch of state rows.
extern __shared__ float sT[];

__global__ void __launch_bounds__(256, 1) backtrace_kernel(float* __restrict__ out)
{
    const int b   = blockIdx.x;
    const int tid = threadIdx.x;

    // fill SMEM transT cache
    for (int idx = tid; idx < SROWS * (KK / 4); idx += 256)
        ((float4*)sT)[idx] = ((const float4*)g_transT)[idx];
    __syncthreads();
    if (tid >= 32) return;
    const int lane = tid;

    // ---- last tag: argmax over state row 1023 (first-index tie-break) ----
    int cur;
    {
        const float4* rp = (const float4*)(g_state + (1023 * BB + b) * KK) + lane * 2;
        float4 sa = __ldg(rp), sb = __ldg(rp + 1);
        unsigned um = fmono(sa.x); int ui = lane * 8;
        unsigned u;
        u = fmono(sa.y); if (u > um) { um = u; ui = lane * 8 + 1; }
        u = fmono(sa.z); if (u > um) { um = u; ui = lane * 8 + 2; }
        u = fmono(sa.w); if (u > um) { um = u; ui = lane * 8 + 3; }
        u = fmono(sb.x); if (u > um) { um = u; ui = lane * 8 + 4; }
        u = fmono(sb.y); if (u > um) { um = u; ui = lane * 8 + 5; }
        u = fmono(sb.z); if (u > um) { um = u; ui = lane * 8 + 6; }
        u = fmono(sb.w); if (u > um) { um = u; ui = lane * 8 + 7; }
        unsigned gmax = __reduce_max_sync(0xffffffffu, um);
        unsigned mask = __ballot_sync(0xffffffffu, um == gmax);
        int lead = __ffs(mask) - 1;
        cur = __shfl_sync(0xffffffffu, ui, lead);
        if (lane == 0) out[b * TT + (TT - 1)] = (float)cur;
    }

    // ---- prefetch pipeline for state rows (independent of chain!) ----
    float4 pfa[4], pfb[4];
    #pragma unroll
    for (int d = 0; d < 4; ++d) {
        const float4* rp = (const float4*)(g_state + ((1022 - d) * BB + b) * KK) + lane * 2;
        pfa[d] = __ldg(rp);
        pfb[d] = __ldg(rp + 1);
    }

    for (int t = TT - 1; t >= 1; --t) {
        const int slot = (TT - 1 - t) & 3;
        float4 sa = pfa[slot], sb = pfb[slot];

        // refill slot with row t-5 (used 4 iterations from now)
        int nrow = t - 5;
        if (nrow >= 0) {
            const float4* rp = (const float4*)(g_state + (nrow * BB + b) * KK) + lane * 2;
            pfa[slot] = __ldg(rp);
            pfb[slot] = __ldg(rp + 1);
        }

        // transT row for current tag: SMEM if cached, else L2
        const float4* trp = (cur < SROWS)
            ? (const float4*)(sT + cur * KK)
            : (const float4*)(g_transT + cur * KK);
        float4 t0 = trp[lane * 2];
        float4 t1 = trp[lane * 2 + 1];

        // two 4-deep chains (lower indices first), then merge: exact first-index
        unsigned umA = fmono(sa.x + t0.x); int uiA = lane * 8;
        unsigned umB = fmono(sb.x + t1.x); int uiB = lane * 8 + 4;
        unsigned u;
        u = fmono(sa.y + t0.y); if (u > umA) { umA = u; uiA = lane * 8 + 1; }
        u = fmono(sb.y + t1.y); if (u > umB) { umB = u; uiB = lane * 8 + 5; }
        u = fmono(sa.z + t0.z); if (u > umA) { umA = u; uiA = lane * 8 + 2; }
        u = fmono(sb.z + t1.z); if (u > umB) { umB = u; uiB = lane * 8 + 6; }
        u = fmono(sa.w + t0.w); if (u > umA) { umA = u; uiA = lane * 8 + 3; }
        u = fmono(sb.w + t1.w); if (u > umB) { umB = u; uiB = lane * 8 + 7; }
        if (umB > umA) { umA = umB; uiA = uiB; }   // strict >: ties keep lower index

        unsigned gmax = __reduce_max_sync(0xffffffffu, umA);
        unsigned mask = __ballot_sync(0xffffffffu, umA == gmax);
        int lead = __ffs(mask) - 1;
        int prev = __shfl_sync(0xffffffffu, uiA, lead);

        if (lane == 0) out[b * TT + (t - 1)] = (float)prev;
        cur = prev;
    }
}

// ---------------- launch ----------------------------------------------------
extern "C" void kernel_launch(void* const* d_in, const int* in_sizes, int n_in,
                              void* d_out, int out_size)
{
    const float* em    = (const float*)d_in[0];  // [B, T, K] fp32
    const float* trans = (const float*)d_in[1];  // [K, K] fp32
    float* out = (float*)d_out;                  // [B, T] fp32

    const int bt_smem = SROWS * KK * (int)sizeof(float);   // 229376
    cudaFuncSetAttribute(backtrace_kernel,
                         cudaFuncAttributeMaxDynamicSharedMemorySize, bt_smem);

    transpose_kernel<<<dim3(8, 8), dim3(32, 8)>>>(trans);
    fwd_kernel<<<2 * BB, 256>>>(em, trans);
    backtrace_kernel<<<BB, 256, bt_smem>>>(out);
}

// round 3
// speedup vs baseline: 1.2202x; 1.2202x over previous
#include <cuda_runtime.h>
#include <cstdint>

#define BB 64
#define TT 1024
#define KK 256
#define HALF 128
#define SROWS 224          // transT rows cached in backtrace SMEM (224 KB)

// ---------------- scratch ---------------------------------------------------
__device__ float g_state[TT * BB * KK];    // all forward states, 64 MB
__device__ float g_transT[KK * KK];        // transposed transitions

// ---------------- helpers ---------------------------------------------------
__device__ __forceinline__ uint32_t smem_u32(const void* p) {
    return (uint32_t)__cvta_generic_to_shared(p);
}

// monotone float->u32 map: preserves ordering exactly (finite values)
__device__ __forceinline__ unsigned fmono(float f) {
    int b = __float_as_int(f);
    return (unsigned)(b ^ ((b >> 31) | 0x80000000));
}

__device__ __forceinline__ void cluster_sync_all() {
    asm volatile("barrier.cluster.arrive.aligned;" ::: "memory");
    asm volatile("barrier.cluster.wait.aligned;" ::: "memory");
}

__device__ __forceinline__ uint32_t mapa_peer(uint32_t laddr, unsigned peer) {
    uint32_t raddr;
    asm volatile("mapa.shared::cluster.u32 %0, %1, %2;"
                 : "=r"(raddr) : "r"(laddr), "r"(peer));
    return raddr;
}

__device__ __forceinline__ void mbar_init(uint32_t addr, unsigned count) {
    asm volatile("mbarrier.init.shared.b64 [%0], %1;" :: "r"(addr), "r"(count) : "memory");
}
__device__ __forceinline__ void mbar_arrive_remote_release(uint32_t raddr) {
    asm volatile("mbarrier.arrive.release.cluster.shared::cluster.b64 _, [%0];"
                 :: "r"(raddr) : "memory");
}
__device__ __forceinline__ void mbar_wait_cluster(uint32_t addr, unsigned parity) {
    asm volatile(
        "{\n\t"
        ".reg .pred P1;\n\t"
        "WAIT_%=:\n\t"
        "mbarrier.try_wait.parity.acquire.cluster.shared::cta.b64 P1, [%0], %1, 0x989680;\n\t"
        "@P1 bra.uni DONE_%=;\n\t"
        "bra.uni WAIT_%=;\n\t"
        "DONE_%=:\n\t"
        "}"
        :: "r"(addr), "r"(parity) : "memory");
}
__device__ __forceinline__ void st_cluster_f32(uint32_t raddr, float v) {
    asm volatile("st.shared::cluster.f32 [%0], %1;" :: "r"(raddr), "f"(v) : "memory");
}

// ---------------- tiny no-op kernels (align ncu capture on fwd = launch #6) -
__global__ void noop_kernel() {}

// ---------------- transpose kernel ------------------------------------------
__global__ void transpose_kernel(const float* __restrict__ trans)
{
    __shared__ float tile[32][33];
    int bx = blockIdx.x, by = blockIdx.y;
    int x = bx * 32 + threadIdx.x;
    #pragma unroll
    for (int r = 0; r < 4; ++r) {
        int y = by * 32 + threadIdx.y + r * 8;
        tile[threadIdx.y + r * 8][threadIdx.x] = trans[y * KK + x];
    }
    __syncthreads();
    int x2 = by * 32 + threadIdx.x;
    #pragma unroll
    for (int r = 0; r < 4; ++r) {
        int y2 = bx * 32 + threadIdx.y + r * 8;
        g_transT[y2 * KK + x2] = tile[threadIdx.x][threadIdx.y + r * 8];
    }
}

// ---------------- forward kernel (values only, phase-split overlap) ---------
// 2-CTA cluster per batch. CTA rank owns j columns [rank*128, rank*128+128),
// trans held entirely in registers (trA = own-half i rows, trB = peer-half).
// Per step: phase A maxes over own-half i (locally produced, no wait), THEN
// wait peer mbarrier (data has been in flight during phase A), phase B maxes
// over peer-half i. One remote arrive + one wait per CTA per step.
__global__ void __cluster_dims__(2, 1, 1) __launch_bounds__(256, 1)
fwd_kernel(const float* __restrict__ em, const float* __restrict__ trans)
{
    __shared__ float st[2][KK];
    __shared__ __align__(8) unsigned long long mbar;

    const int bid  = blockIdx.x;
    const int b    = bid >> 1;
    const unsigned rank = bid & 1;
    const unsigned peer = rank ^ 1u;
    const int tid  = threadIdx.x;
    const int w    = tid >> 5;
    const int lane = tid & 31;
    const int q    = lane & 3;
    const int g    = lane >> 2;
    const int jcol = rank * HALF + w * 16 + q * 4;   // this thread's j quad

    const uint32_t mbar_l = smem_u32(&mbar);
    if (tid == 0) mbar_init(mbar_l, 1);              // 1 remote arrive per phase

    // transition registers
    float4 trA[16], trB[16];
    #pragma unroll
    for (int k = 0; k < 16; ++k)
        trA[k] = *(const float4*)&trans[(rank * HALF + k * 8 + g) * KK + jcol];
    #pragma unroll
    for (int k = 0; k < 16; ++k)
        trB[k] = *(const float4*)&trans[(peer * HALF + k * 8 + g) * KK + jcol];

    // initial state = emissions[b,0,:] (both CTAs load full row locally)
    {
        float v = em[(b * TT) * KK + tid];
        st[0][tid] = v;
        if (rank == 0) g_state[b * KK + tid] = v;
    }
    __syncthreads();
    cluster_sync_all();          // peer mbar init + st[0] ready on both sides

    const uint32_t mbar_r = mapa_peer(mbar_l, peer);
    unsigned par = 0;

    // software-pipelined emission (one step ahead)
    float4 emCur = make_float4(0.f, 0.f, 0.f, 0.f);
    const bool writer = (lane < 4);
    const int jW = rank * HALF + w * 16 + lane * 4;  // writer quad (lane=q here)
    if (writer)
        emCur = __ldg((const float4*)&em[((b * TT + 1) * KK) + jW]);

    for (int t = 1; t < TT; ++t) {
        const float* cur = st[(t + 1) & 1];
        float*       nxt = st[t & 1];

        // prefetch next step's emission
        float4 emNxt = make_float4(0.f, 0.f, 0.f, 0.f);
        if (writer && (t + 1 < TT))
            emNxt = __ldg((const float4*)&em[((b * TT + t + 1) * KK) + jW]);

        // ---- phase A: own-half i (local data, no wait) ----
        float a0, a1, a2, a3;
        {
            float sv = cur[rank * HALF + g];
            a0 = sv + trA[0].x; a1 = sv + trA[0].y;
            a2 = sv + trA[0].z; a3 = sv + trA[0].w;
        }
        #pragma unroll
        for (int k = 1; k < 16; ++k) {
            float sv = cur[rank * HALF + k * 8 + g];
            a0 = fmaxf(a0, sv + trA[k].x);
            a1 = fmaxf(a1, sv + trA[k].y);
            a2 = fmaxf(a2, sv + trA[k].z);
            a3 = fmaxf(a3, sv + trA[k].w);
        }

        // ---- wait for peer half of state(t-1) (in flight during phase A) ----
        if (t >= 2) {
            mbar_wait_cluster(mbar_l, par);
            par ^= 1u;
        }

        // ---- phase B: peer-half i ----
        #pragma unroll
        for (int k = 0; k < 16; ++k) {
            float sv = cur[peer * HALF + k * 8 + g];
            a0 = fmaxf(a0, sv + trB[k].x);
            a1 = fmaxf(a1, sv + trB[k].y);
            a2 = fmaxf(a2, sv + trB[k].z);
            a3 = fmaxf(a3, sv + trB[k].w);
        }

        // butterfly max over the 8 i-subgroups (lanes with same q)
        #pragma unroll
        for (int off = 4; off <= 16; off <<= 1) {
            a0 = fmaxf(a0, __shfl_xor_sync(0xffffffffu, a0, off));
            a1 = fmaxf(a1, __shfl_xor_sync(0xffffffffu, a1, off));
            a2 = fmaxf(a2, __shfl_xor_sync(0xffffffffu, a2, off));
            a3 = fmaxf(a3, __shfl_xor_sync(0xffffffffu, a3, off));
        }

        if (writer) {
            float4 ns = make_float4(a0 + emCur.x, a1 + emCur.y,
                                    a2 + emCur.z, a3 + emCur.w);
            *(float4*)&nxt[jW] = ns;                              // local copy
            uint32_t r = mapa_peer(smem_u32(&nxt[jW]), peer);     // peer copy
            st_cluster_f32(r,      ns.x);
            st_cluster_f32(r + 4,  ns.y);
            st_cluster_f32(r + 8,  ns.z);
            st_cluster_f32(r + 12, ns.w);
            *(float4*)&g_state[(t * BB + b) * KK + jW] = ns;      // for backtrace
        }
        emCur = emNxt;

        __syncthreads();                     // all stores issued (cumulativity)
        if (tid == 0)
            mbar_arrive_remote_release(mbar_r);   // signal peer: data en route
    }

    cluster_sync_all();   // keep SMEM alive until peer consumed last arrival
}

// ---------------- backtrace: serial argmax recompute along decoded path -----
extern __shared__ float sT[];

__global__ void __launch_bounds__(256, 1) backtrace_kernel(float* __restrict__ out)
{
    const int b   = blockIdx.x;
    const int tid = threadIdx.x;

    for (int idx = tid; idx < SROWS * (KK / 4); idx += 256)
        ((float4*)sT)[idx] = ((const float4*)g_transT)[idx];
    __syncthreads();
    if (tid >= 32) return;
    const int lane = tid;

    // ---- last tag: argmax over state row 1023 (first-index tie-break) ----
    int cur;
    {
        const float4* rp = (const float4*)(g_state + (1023 * BB + b) * KK) + lane * 2;
        float4 sa = __ldg(rp), sb = __ldg(rp + 1);
        unsigned um = fmono(sa.x); int ui = lane * 8;
        unsigned u;
        u = fmono(sa.y); if (u > um) { um = u; ui = lane * 8 + 1; }
        u = fmono(sa.z); if (u > um) { um = u; ui = lane * 8 + 2; }
        u = fmono(sa.w); if (u > um) { um = u; ui = lane * 8 + 3; }
        u = fmono(sb.x); if (u > um) { um = u; ui = lane * 8 + 4; }
        u = fmono(sb.y); if (u > um) { um = u; ui = lane * 8 + 5; }
        u = fmono(sb.z); if (u > um) { um = u; ui = lane * 8 + 6; }
        u = fmono(sb.w); if (u > um) { um = u; ui = lane * 8 + 7; }
        unsigned gmax = __reduce_max_sync(0xffffffffu, um);
        unsigned mask = __ballot_sync(0xffffffffu, um == gmax);
        int lead = __ffs(mask) - 1;
        cur = __shfl_sync(0xffffffffu, ui, lead);
        if (lane == 0) out[b * TT + (TT - 1)] = (float)cur;
    }

    // depth-4 register prefetch of state rows (addresses independent of chain)
    float4 pfa[4], pfb[4];
    #pragma unroll
    for (int d = 0; d < 4; ++d) {
        const float4* rp = (const float4*)(g_state + ((1022 - d) * BB + b) * KK) + lane * 2;
        pfa[d] = __ldg(rp);
        pfb[d] = __ldg(rp + 1);
    }

    for (int t = TT - 1; t >= 1; --t) {
        const int slot = (TT - 1 - t) & 3;
        float4 sa = pfa[slot], sb = pfb[slot];

        int nrow = t - 5;
        if (nrow >= 0) {
            const float4* rp = (const float4*)(g_state + (nrow * BB + b) * KK) + lane * 2;
            pfa[slot] = __ldg(rp);
            pfb[slot] = __ldg(rp + 1);
        }

        const float4* trp = (cur < SROWS)
            ? (const float4*)(sT + cur * KK)
            : (const float4*)(g_transT + cur * KK);
        float4 t0 = trp[lane * 2];
        float4 t1 = trp[lane * 2 + 1];

        unsigned umA = fmono(sa.x + t0.x); int uiA = lane * 8;
        unsigned umB = fmono(sb.x + t1.x); int uiB = lane * 8 + 4;
        unsigned u;
        u = fmono(sa.y + t0.y); if (u > umA) { umA = u; uiA = lane * 8 + 1; }
        u = fmono(sb.y + t1.y); if (u > umB) { umB = u; uiB = lane * 8 + 5; }
        u = fmono(sa.z + t0.z); if (u > umA) { umA = u; uiA = lane * 8 + 2; }
        u = fmono(sb.z + t1.z); if (u > umB) { umB = u; uiB = lane * 8 + 6; }
        u = fmono(sa.w + t0.w); if (u > umA) { umA = u; uiA = lane * 8 + 3; }
        u = fmono(sb.w + t1.w); if (u > umB) { umB = u; uiB = lane * 8 + 7; }
        if (umB > umA) { umA = umB; uiA = uiB; }   // strict >: lower index wins ties

        unsigned gmax = __reduce_max_sync(0xffffffffu, umA);
        unsigned mask = __ballot_sync(0xffffffffu, umA == gmax);
        int lead = __ffs(mask) - 1;
        int prev = __shfl_sync(0xffffffffu, uiA, lead);

        if (lane == 0) out[b * TT + (t - 1)] = (float)prev;
        cur = prev;
    }
}

// ---------------- launch ----------------------------------------------------
extern "C" void kernel_launch(void* const* d_in, const int* in_sizes, int n_in,
                              void* d_out, int out_size)
{
    const float* em    = (const float*)d_in[0];  // [B, T, K] fp32
    const float* trans = (const float*)d_in[1];  // [K, K] fp32
    float* out = (float*)d_out;                  // [B, T] fp32

    const int bt_smem = SROWS * KK * (int)sizeof(float);   // 229376
    cudaFuncSetAttribute(backtrace_kernel,
                         cudaFuncAttributeMaxDynamicSharedMemorySize, bt_smem);

    transpose_kernel<<<dim3(8, 8), dim3(32, 8)>>>(trans);   // launch 1
    noop_kernel<<<1, 32>>>();                               // launch 2
    noop_kernel<<<1, 32>>>();                               // launch 3
    noop_kernel<<<1, 32>>>();                               // launch 4
    noop_kernel<<<1, 32>>>();                               // launch 5
    fwd_kernel<<<2 * BB, 256>>>(em, trans);                 // launch 6 <- ncu
    backtrace_kernel<<<BB, 256, bt_smem>>>(out);            // launch 7
}